// round 1
// baseline (speedup 1.0000x reference)
#include <cuda_runtime.h>

#define LL      128
#define NANG    120
#define TB      128     // threads per CTA
#define TILE_X  16
#define TILE_Y  8
#define ZC      32      // z elements per CTA
#define ROWS    21      // max image rows needed per tile per angle (span<=16.6 +taps +margin)
#define RSTRIDE 36      // smem row stride in floats (bank-skewed, 16B-aligned)

// ---- packed f32x2 helpers (Blackwell FFMA2 path) ----
__device__ __forceinline__ unsigned long long pack2(float x, float y) {
    unsigned long long r;
    asm("mov.b64 %0, {%1, %2};" : "=l"(r) : "f"(x), "f"(y));
    return r;
}
__device__ __forceinline__ void ffma2(unsigned long long &acc, unsigned long long v,
                                      unsigned long long w) {
    asm("fma.rn.f32x2 %0, %1, %2, %0;" : "+l"(acc) : "l"(v), "l"(w));
}
__device__ __forceinline__ void unpack2(unsigned long long v, float &x, float &y) {
    asm("mov.b64 {%0, %1}, %2;" : "=f"(x), "=f"(y) : "l"(v));
}
__device__ __forceinline__ void lds2(unsigned long long &a, unsigned long long &b,
                                     unsigned addr) {
    asm volatile("ld.shared.v2.u64 {%0, %1}, [%2];" : "=l"(a), "=l"(b) : "r"(addr));
}

// stage ROWS image rows (each ZC floats, clamped y) into smem buffer
__device__ __forceinline__ void stage_rows(float *dst, const float * __restrict__ img_a,
                                           int ymin, int tid) {
    #pragma unroll
    for (int i = tid; i < ROWS * ZC; i += TB) {
        int r  = i >> 5;      // ZC == 32
        int zz = i & 31;
        int gy = min(max(ymin + r, 0), LL - 1);
        dst[r * RSTRIDE + zz] = __ldg(img_a + gy * LL + zz);
    }
}

__device__ __forceinline__ void compute_angle(float c, float s, int ymin, unsigned smbase,
                                              float Xp, float Yp,
                                              unsigned long long acc[ZC / 2], float &nrm) {
    float sxv = fmaf(c, Xp, fmaf(s, Yp, 63.5f));
    float syv = fmaf(c, Yp, fmaf(-s, Xp, 63.5f));
    float x0f = floorf(sxv), y0f = floorf(syv);
    float wx = sxv - x0f, wy = syv - y0f;
    int x0 = (int)x0f, y0 = (int)y0f;

    float hx = 0.0f;
    if ((unsigned)x0 < (unsigned)LL)       hx = 1.0f - wx;
    if ((unsigned)(x0 + 1) < (unsigned)LL) hx += wx;
    float A0 = ((unsigned)y0 < (unsigned)LL)       ? hx * (1.0f - wy) : 0.0f;
    float A1 = ((unsigned)(y0 + 1) < (unsigned)LL) ? hx * wy          : 0.0f;
    nrm += A0 + A1;

    int r0 = y0 - ymin;
    r0 = min(max(r0, 0), ROWS - 2);   // defensive; analytically always in range
    unsigned a0 = smbase + (unsigned)(r0 * (RSTRIDE * 4));
    unsigned long long W0 = pack2(A0, A0), W1 = pack2(A1, A1);

    #pragma unroll
    for (int q = 0; q < 8; ++q) {
        unsigned long long p0, p1, q0, q1;
        lds2(p0, p1, a0 + q * 16);
        lds2(q0, q1, a0 + RSTRIDE * 4 + q * 16);
        ffma2(acc[2 * q],     p0, W0);
        ffma2(acc[2 * q + 1], p1, W0);
        ffma2(acc[2 * q],     q0, W1);
        ffma2(acc[2 * q + 1], q1, W1);
    }
}

__global__ __launch_bounds__(TB, 5)
void bp_kernel(const float * __restrict__ image, const float * __restrict__ angles,
               float * __restrict__ out) {
    __shared__ float2 s_tab[NANG];
    __shared__ float  s_img[2][ROWS * RSTRIDE];

    const int tid = threadIdx.x;
    if (tid < NANG) {
        float ph = -angles[tid] * 0.017453292519943295f;  // phi = -deg2rad(angle)
        float sv, cv;
        sincosf(ph, &sv, &cv);
        s_tab[tid] = make_float2(cv, sv);
    }

    const int tileX0 = (blockIdx.x & 7) * TILE_X;
    const int tileY0 = (blockIdx.x >> 3) * TILE_Y;
    const int z0 = blockIdx.y * ZC;
    const int b  = blockIdx.z;

    const int warp = tid >> 5, lane = tid & 31;
    const int px = tileX0 + (warp & 1) * 8 + (lane & 7);   // warp covers 8x4 pixels
    const int py = tileY0 + (warp >> 1) * 4 + (lane >> 3);
    const float Xp = px - 63.5f, Yp = py - 63.5f;
    const float X0f = tileX0 - 63.5f, X1f = X0f + (TILE_X - 1);
    const float Y0f = tileY0 - 63.5f, Y1f = Y0f + (TILE_Y - 1);

    const float *img_b = image + (size_t)b * NANG * LL * LL + z0;

    unsigned long long acc[ZC / 2];
    #pragma unroll
    for (int i = 0; i < ZC / 2; ++i) acc[i] = 0ULL;
    float nrm = 0.0f;

    __syncthreads();  // s_tab ready

    const unsigned sm_base0 = (unsigned)__cvta_generic_to_shared(&s_img[0][0]);
    const unsigned sm_base1 = (unsigned)__cvta_generic_to_shared(&s_img[1][0]);

    // prologue: stage angle 0 into buffer 0
    float2 cs_cur = s_tab[0];
    int ymin_cur;
    {
        float cv = cs_cur.x, sv = cs_cur.y;
        float m = fminf(-sv * X0f, -sv * X1f) + fminf(cv * Y0f, cv * Y1f) + 63.5f;
        ymin_cur = (int)floorf(m) - 1;
        stage_rows(&s_img[0][0], img_b, ymin_cur, tid);
    }

    float2 cs_nxt = cs_cur;
    int ymin_nxt = ymin_cur;

    for (int a = 0; a < NANG; ++a) {
        __syncthreads();  // buf[a&1] staged & visible; buf[(a+1)&1] free to overwrite
        if (a + 1 < NANG) {
            cs_nxt = s_tab[a + 1];
            float cv = cs_nxt.x, sv = cs_nxt.y;
            float m = fminf(-sv * X0f, -sv * X1f) + fminf(cv * Y0f, cv * Y1f) + 63.5f;
            ymin_nxt = (int)floorf(m) - 1;
            stage_rows(&s_img[(a + 1) & 1][0], img_b + (size_t)(a + 1) * LL * LL,
                       ymin_nxt, tid);
        }
        unsigned smb = (a & 1) ? sm_base1 : sm_base0;
        compute_angle(cs_cur.x, cs_cur.y, ymin_cur, smb, Xp, Yp, acc, nrm);
        cs_cur = cs_nxt;
        ymin_cur = ymin_nxt;
    }

    // epilogue: out = obj / (norm + delta)
    float inv = 1.0f / (nrm + 1e-11f);
    float *op = out + (((size_t)b * LL + px) * LL + py) * LL + z0;
    #pragma unroll
    for (int q = 0; q < 8; ++q) {
        float ax, ay, bx, by;
        unpack2(acc[2 * q],     ax, ay);
        unpack2(acc[2 * q + 1], bx, by);
        float4 v = make_float4(ax * inv, ay * inv, bx * inv, by * inv);
        *reinterpret_cast<float4 *>(op + q * 4) = v;
    }
}

extern "C" void kernel_launch(void *const *d_in, const int *in_sizes, int n_in,
                              void *d_out, int out_size) {
    const float *image  = (const float *)d_in[0];
    const float *angles = (const float *)d_in[1];
    float *out = (float *)d_out;
    dim3 grid(128 /* 8 x-tiles * 16 y-tiles */, LL / ZC /*4*/, 2 /*B*/);
    bp_kernel<<<grid, TB>>>(image, angles, out);
}

// round 2
// speedup vs baseline: 1.0146x; 1.0146x over previous
#include <cuda_runtime.h>

#define LL      128
#define NANG    120
#define TB      128     // threads per CTA
#define TILE_X  16
#define TILE_Y  8
#define ZC      32      // z elements per CTA
#define ROWS    24      // staged rows per angle (need <=21; 24 = 6*TB/ZC exact)
#define RSTRIDE 36      // smem row stride in floats (bank-skewed, 16B-aligned)

// ---- packed f32x2 helpers (Blackwell FFMA2 path) ----
__device__ __forceinline__ unsigned long long pack2(float x, float y) {
    unsigned long long r;
    asm("mov.b64 %0, {%1, %2};" : "=l"(r) : "f"(x), "f"(y));
    return r;
}
__device__ __forceinline__ void ffma2(unsigned long long &acc, unsigned long long v,
                                      unsigned long long w) {
    asm("fma.rn.f32x2 %0, %1, %2, %0;" : "+l"(acc) : "l"(v), "l"(w));
}
__device__ __forceinline__ void unpack2(unsigned long long v, float &x, float &y) {
    asm("mov.b64 {%0, %1}, %2;" : "=f"(x), "=f"(y) : "l"(v));
}
__device__ __forceinline__ void lds2(unsigned long long &a, unsigned long long &b,
                                     unsigned addr) {
    asm volatile("ld.shared.v2.u64 {%0, %1}, [%2];" : "=l"(a), "=l"(b) : "r"(addr));
}

// stage ROWS image rows (each ZC floats, clamped y) into smem buffer
// ROWS*ZC = 768 = 6*TB exactly -> 6 unpredicated iterations
__device__ __forceinline__ void stage_rows(float *dst, const float * __restrict__ img_a,
                                           int ymin, int tid) {
    #pragma unroll
    for (int k = 0; k < (ROWS * ZC) / TB; ++k) {
        int i  = tid + k * TB;
        int r  = i >> 5;      // ZC == 32
        int zz = i & 31;
        int gy = min(max(ymin + r, 0), LL - 1);
        dst[r * RSTRIDE + zz] = __ldg(img_a + gy * LL + zz);
    }
}

__device__ __forceinline__ void compute_angle(float c, float s, int ymin, unsigned smbase,
                                              float Xp, float Yp,
                                              unsigned long long acc[ZC / 2], float &nrm) {
    float sxv = fmaf(c, Xp, fmaf(s, Yp, 63.5f));
    float syv = fmaf(c, Yp, fmaf(-s, Xp, 63.5f));
    float x0f = floorf(sxv), y0f = floorf(syv);
    float wx = sxv - x0f, wy = syv - y0f;
    int x0 = (int)x0f, y0 = (int)y0f;

    float hx = 0.0f;
    if ((unsigned)x0 < (unsigned)LL)       hx = 1.0f - wx;
    if ((unsigned)(x0 + 1) < (unsigned)LL) hx += wx;
    float A0 = ((unsigned)y0 < (unsigned)LL)       ? hx * (1.0f - wy) : 0.0f;
    float A1 = ((unsigned)(y0 + 1) < (unsigned)LL) ? hx * wy          : 0.0f;
    nrm += A0 + A1;

    int r0 = y0 - ymin;
    r0 = min(max(r0, 0), ROWS - 2);   // defensive; analytically always in range
    unsigned a0 = smbase + (unsigned)(r0 * (RSTRIDE * 4));
    unsigned long long W0 = pack2(A0, A0), W1 = pack2(A1, A1);

    #pragma unroll
    for (int q = 0; q < 8; ++q) {
        unsigned long long p0, p1, q0, q1;
        lds2(p0, p1, a0 + q * 16);
        lds2(q0, q1, a0 + RSTRIDE * 4 + q * 16);
        ffma2(acc[2 * q],     p0, W0);
        ffma2(acc[2 * q + 1], p1, W0);
        ffma2(acc[2 * q],     q0, W1);
        ffma2(acc[2 * q + 1], q1, W1);
    }
}

// 7 blocks/SM * 148 SMs = 1036 >= 1024 CTAs -> entire grid is ONE resident wave
__global__ __launch_bounds__(TB, 7)
void bp_kernel(const float * __restrict__ image, const float * __restrict__ angles,
               float * __restrict__ out) {
    __shared__ float2 s_tab[NANG];
    __shared__ float  s_img[2][ROWS * RSTRIDE];

    const int tid = threadIdx.x;
    if (tid < NANG) {
        float ph = -angles[tid] * 0.017453292519943295f;  // phi = -deg2rad(angle)
        float sv, cv;
        sincosf(ph, &sv, &cv);
        s_tab[tid] = make_float2(cv, sv);
    }

    const int tileX0 = (blockIdx.x & 7) * TILE_X;
    const int tileY0 = (blockIdx.x >> 3) * TILE_Y;
    const int z0 = blockIdx.y * ZC;
    const int b  = blockIdx.z;

    const int warp = tid >> 5, lane = tid & 31;
    const int px = tileX0 + (warp & 1) * 8 + (lane & 7);   // warp covers 8x4 pixels
    const int py = tileY0 + (warp >> 1) * 4 + (lane >> 3);
    const float Xp = px - 63.5f, Yp = py - 63.5f;
    const float X0f = tileX0 - 63.5f, X1f = X0f + (TILE_X - 1);
    const float Y0f = tileY0 - 63.5f, Y1f = Y0f + (TILE_Y - 1);

    const float *img_b = image + (size_t)b * NANG * LL * LL + z0;

    unsigned long long acc[ZC / 2];
    #pragma unroll
    for (int i = 0; i < ZC / 2; ++i) acc[i] = 0ULL;
    float nrm = 0.0f;

    __syncthreads();  // s_tab ready

    const unsigned sm_base0 = (unsigned)__cvta_generic_to_shared(&s_img[0][0]);

    // prologue: stage angle 0 into buffer 0
    int ymin_cur;
    {
        float2 cs = s_tab[0];
        float m = fminf(-cs.y * X0f, -cs.y * X1f) + fminf(cs.x * Y0f, cs.x * Y1f) + 63.5f;
        ymin_cur = (int)floorf(m) - 1;
        stage_rows(&s_img[0][0], img_b, ymin_cur, tid);
    }

    for (int a = 0; a < NANG; ++a) {
        __syncthreads();  // buf[a&1] staged & visible; buf[(a+1)&1] free to overwrite
        int ymin_nxt = ymin_cur;
        if (a + 1 < NANG) {
            float2 cs = s_tab[a + 1];
            float m = fminf(-cs.y * X0f, -cs.y * X1f) + fminf(cs.x * Y0f, cs.x * Y1f) + 63.5f;
            ymin_nxt = (int)floorf(m) - 1;
            stage_rows(&s_img[(a + 1) & 1][0], img_b + (size_t)(a + 1) * LL * LL,
                       ymin_nxt, tid);
        }
        float2 cs = s_tab[a];
        unsigned smb = sm_base0 + (unsigned)((a & 1) * (ROWS * RSTRIDE * 4));
        compute_angle(cs.x, cs.y, ymin_cur, smb, Xp, Yp, acc, nrm);
        ymin_cur = ymin_nxt;
    }

    // epilogue: out = obj / (norm + delta)
    float inv = 1.0f / (nrm + 1e-11f);
    float *op = out + (((size_t)b * LL + px) * LL + py) * LL + z0;
    #pragma unroll
    for (int q = 0; q < 8; ++q) {
        float ax, ay, bx, by;
        unpack2(acc[2 * q],     ax, ay);
        unpack2(acc[2 * q + 1], bx, by);
        float4 v = make_float4(ax * inv, ay * inv, bx * inv, by * inv);
        *reinterpret_cast<float4 *>(op + q * 4) = v;
    }
}

extern "C" void kernel_launch(void *const *d_in, const int *in_sizes, int n_in,
                              void *d_out, int out_size) {
    const float *image  = (const float *)d_in[0];
    const float *angles = (const float *)d_in[1];
    float *out = (float *)d_out;
    dim3 grid(128 /* 8 x-tiles * 16 y-tiles */, LL / ZC /*4*/, 2 /*B*/);
    bp_kernel<<<grid, TB>>>(image, angles, out);
}

// round 3
// speedup vs baseline: 1.1297x; 1.1135x over previous
#include <cuda_runtime.h>

#define LL    128
#define NANG  120
#define TB    128
#define TX    16      // CTA px extent
#define TY    16      // CTA py extent (8 pairs of py)
#define ZC    16      // z per thread (per pixel)
#define ROWS  32      // staged rows per angle (need <=27)
#define RS    20      // smem row stride in floats (80B: bank cycle 8, 16B aligned)

// ---- packed f32x2 helpers ----
__device__ __forceinline__ unsigned long long pack2(float x, float y) {
    unsigned long long r;
    asm("mov.b64 %0, {%1, %2};" : "=l"(r) : "f"(x), "f"(y));
    return r;
}
__device__ __forceinline__ void ffma2(unsigned long long &acc, unsigned long long v,
                                      unsigned long long w) {
    asm("fma.rn.f32x2 %0, %1, %2, %0;" : "+l"(acc) : "l"(v), "l"(w));
}
__device__ __forceinline__ void unpack2(unsigned long long v, float &x, float &y) {
    asm("mov.b64 {%0, %1}, %2;" : "=f"(x), "=f"(y) : "l"(v));
}
__device__ __forceinline__ void lds2(unsigned long long &a, unsigned long long &b,
                                     unsigned addr) {
    asm volatile("ld.shared.v2.u64 {%0, %1}, [%2];" : "=l"(a), "=l"(b) : "r"(addr));
}

// stage ROWS rows x 16 z floats; ROWS*ZC = 512 = 4*TB exact
__device__ __forceinline__ void stage_rows(float *dst, const float * __restrict__ img_a,
                                           int ymin, int tid) {
    const int z = tid & 15;
    const int rbase = tid >> 4;
    #pragma unroll
    for (int k = 0; k < 4; ++k) {
        int r  = rbase + 8 * k;
        int gy = min(max(ymin + r, 0), LL - 1);
        dst[r * RS + z] = __ldg(img_a + gy * LL + z);
    }
}

__global__ __launch_bounds__(TB, 7)
void bp_kernel(const float * __restrict__ image, const float * __restrict__ angles,
               float * __restrict__ out) {
    __shared__ float2 s_tab[NANG];
    __shared__ __align__(16) float s_img[2][ROWS * RS];

    const int tid = threadIdx.x;
    if (tid < NANG) {
        float ph = -angles[tid] * 0.017453292519943295f;
        float sv, cv;
        sincosf(ph, &sv, &cv);
        s_tab[tid] = make_float2(cv, sv);
    }

    const int tileX0 = (blockIdx.x & 7) * TX;
    const int tileY0 = (blockIdx.x >> 3) * TY;
    const int z0 = blockIdx.y * ZC;
    const int b  = blockIdx.z;

    const int warp = tid >> 5, lane = tid & 31;
    const int px = tileX0 + (warp & 1) * 8 + (lane & 7);
    const int pr = (warp >> 1) * 4 + (lane >> 3);      // pair index 0..7
    const int py = tileY0 + 2 * pr;                    // pixel1; pixel2 = py+1
    const float Xp = px - 63.5f, Yp = py - 63.5f;
    const float X0f = tileX0 - 63.5f, X1f = X0f + (TX - 1);
    const float Y0f = tileY0 - 63.5f, Y1f = Y0f + (TY - 1);

    const float *img_b = image + (size_t)b * NANG * LL * LL + z0;

    unsigned long long acc[16];          // [0..7]=pixel1 (16 z), [8..15]=pixel2
    #pragma unroll
    for (int i = 0; i < 16; ++i) acc[i] = 0ULL;
    float n1 = 0.0f, n2 = 0.0f;

    __syncthreads();  // s_tab ready

    const unsigned sm0 = (unsigned)__cvta_generic_to_shared(&s_img[0][0]);

    int ymin_cur;
    {
        float2 cs = s_tab[0];
        float m = fminf(-cs.y * X0f, -cs.y * X1f) + fminf(cs.x * Y0f, cs.x * Y1f) + 63.5f;
        ymin_cur = (int)floorf(m) - 1;
        stage_rows(&s_img[0][0], img_b, ymin_cur, tid);
    }

    for (int a = 0; a < NANG; ++a) {
        __syncthreads();
        int ymin_nxt = ymin_cur;
        if (a + 1 < NANG) {
            float2 csn = s_tab[a + 1];
            float m = fminf(-csn.y * X0f, -csn.y * X1f) + fminf(csn.x * Y0f, csn.x * Y1f) + 63.5f;
            ymin_nxt = (int)floorf(m) - 1;
            stage_rows(&s_img[(a + 1) & 1][0], img_b + (size_t)(a + 1) * LL * LL,
                       ymin_nxt, tid);
        }

        const float2 cs = s_tab[a];
        const float c = cs.x, s = cs.y;

        // pixel1 weights
        float sx = fmaf(c, Xp, fmaf(s, Yp, 63.5f));
        float sy = fmaf(c, Yp, fmaf(-s, Xp, 63.5f));
        // pixel2 = (px, py+1): d(sx)/dpy = s, d(sy)/dpy = c
        float sx2 = sx + s;
        float sy2 = sy + c;

        float x0f = floorf(sx), y0f = floorf(sy);
        float x2f = floorf(sx2), y2f = floorf(sy2);
        float wx = sx - x0f, wy = sy - y0f;
        float wx2 = sx2 - x2f, wy2 = sy2 - y2f;
        int x0 = (int)x0f, y0 = (int)y0f;
        int x2 = (int)x2f, y2 = (int)y2f;

        float hx = 0.0f;
        if ((unsigned)x0 < (unsigned)LL)       hx = 1.0f - wx;
        if ((unsigned)(x0 + 1) < (unsigned)LL) hx += wx;
        float A0 = ((unsigned)y0 < (unsigned)LL)       ? hx * (1.0f - wy) : 0.0f;
        float A1 = ((unsigned)(y0 + 1) < (unsigned)LL) ? hx * wy          : 0.0f;

        float hx2 = 0.0f;
        if ((unsigned)x2 < (unsigned)LL)       hx2 = 1.0f - wx2;
        if ((unsigned)(x2 + 1) < (unsigned)LL) hx2 += wx2;
        float B0 = ((unsigned)y2 < (unsigned)LL)       ? hx2 * (1.0f - wy2) : 0.0f;
        float B1 = ((unsigned)(y2 + 1) < (unsigned)LL) ? hx2 * wy2          : 0.0f;

        n1 += A0 + A1;
        n2 += B0 + B1;

        // 3-row window: rows base, base+1, base+2 with base = min(y0, y2)
        int d = y2 - y0;                   // in {-1, 0, 1}
        bool dneg = (d < 0), dpos = (d > 0), dd = (d != 0);
        int base = min(y0, y2);

        unsigned long long Wa0 = pack2(dneg ? 0.0f : A0, dneg ? 0.0f : A0);
        unsigned long long Wa1 = pack2(dneg ? A0 : A1,   dneg ? A0 : A1);
        unsigned long long Wa2 = pack2(dneg ? A1 : 0.0f, dneg ? A1 : 0.0f);
        unsigned long long Wb0 = pack2(dpos ? 0.0f : B0, dpos ? 0.0f : B0);
        unsigned long long Wb1 = pack2(dpos ? B0 : B1,   dpos ? B0 : B1);
        unsigned long long Wb2 = pack2(dpos ? B1 : 0.0f, dpos ? B1 : 0.0f);

        unsigned r0 = (unsigned)(base - ymin_cur);   // analytically in [0, ROWS-3]
        unsigned a0addr = sm0 + (unsigned)((a & 1) * (ROWS * RS * 4)) + r0 * (RS * 4);

        #pragma unroll
        for (int q = 0; q < 4; ++q) {
            unsigned long long p00, p01, p10, p11;
            unsigned long long p20 = 0ULL, p21 = 0ULL;
            lds2(p00, p01, a0addr + q * 16);
            lds2(p10, p11, a0addr + RS * 4 + q * 16);
            if (dd) lds2(p20, p21, a0addr + 2 * RS * 4 + q * 16);
            ffma2(acc[2 * q],     p00, Wa0);
            ffma2(acc[2 * q + 1], p01, Wa0);
            ffma2(acc[2 * q],     p10, Wa1);
            ffma2(acc[2 * q + 1], p11, Wa1);
            ffma2(acc[2 * q],     p20, Wa2);
            ffma2(acc[2 * q + 1], p21, Wa2);
            ffma2(acc[8 + 2 * q],     p00, Wb0);
            ffma2(acc[8 + 2 * q + 1], p01, Wb0);
            ffma2(acc[8 + 2 * q],     p10, Wb1);
            ffma2(acc[8 + 2 * q + 1], p11, Wb1);
            ffma2(acc[8 + 2 * q],     p20, Wb2);
            ffma2(acc[8 + 2 * q + 1], p21, Wb2);
        }
        ymin_cur = ymin_nxt;
    }

    // epilogue
    float inv1 = 1.0f / (n1 + 1e-11f);
    float inv2 = 1.0f / (n2 + 1e-11f);
    float *op = out + (((size_t)b * LL + px) * LL + py) * LL + z0;
    #pragma unroll
    for (int q = 0; q < 4; ++q) {
        float ax, ay, bx, by;
        unpack2(acc[2 * q],     ax, ay);
        unpack2(acc[2 * q + 1], bx, by);
        *reinterpret_cast<float4 *>(op + q * 4) =
            make_float4(ax * inv1, ay * inv1, bx * inv1, by * inv1);
    }
    float *op2 = op + LL;  // py+1
    #pragma unroll
    for (int q = 0; q < 4; ++q) {
        float ax, ay, bx, by;
        unpack2(acc[8 + 2 * q],     ax, ay);
        unpack2(acc[8 + 2 * q + 1], bx, by);
        *reinterpret_cast<float4 *>(op2 + q * 4) =
            make_float4(ax * inv2, ay * inv2, bx * inv2, by * inv2);
    }
}

extern "C" void kernel_launch(void *const *d_in, const int *in_sizes, int n_in,
                              void *d_out, int out_size) {
    const float *image  = (const float *)d_in[0];
    const float *angles = (const float *)d_in[1];
    float *out = (float *)d_out;
    dim3 grid(64 /* 8x8 pixel tiles (16x16 each) */, LL / ZC /*8*/, 2 /*B*/);
    bp_kernel<<<grid, TB>>>(image, angles, out);
}